// round 6
// baseline (speedup 1.0000x reference)
#include <cuda_runtime.h>

#define NW      10000
#define MAXLEN  14
#define QCOUNT  32     // BSZ*SEQ
#define TPB     64
#define SORT_B  256
#define NSB     ((NW + SORT_B - 1) / SORT_B)

// Scratch (no allocation allowed)
__device__ int   g_wlen_s[NW];
__device__ int   g_orig_s[NW];
__device__ uint4 g_packed[NW];

// -------------------------------------------------------------------------
// Fused counting-sort: each block rescans wl (L2-hot) for global +
// before-block histograms; no inter-block deps, single launch.
// -------------------------------------------------------------------------
__global__ void __launch_bounds__(SORT_B)
fused_sort_kernel(const int* __restrict__ words, const int* __restrict__ wl) {
    __shared__ int h_all[MAXLEN + 2];
    __shared__ int h_bef[MAXLEN + 2];
    __shared__ int h_rank[MAXLEN + 2];
    __shared__ int base[MAXLEN + 2];

    const int t = threadIdx.x;
    const int blockStart = blockIdx.x * SORT_B;

    if (t <= MAXLEN + 1) { h_all[t] = 0; h_bef[t] = 0; h_rank[t] = 0; }
    __syncthreads();

    const uint4* wl4 = (const uint4*)wl;
    for (int v = t; v < NW / 4; v += SORT_B) {
        uint4 w4 = wl4[v];
        int idx = v * 4;
        atomicAdd(&h_all[w4.x], 1); if (idx + 0 < blockStart) atomicAdd(&h_bef[w4.x], 1);
        atomicAdd(&h_all[w4.y], 1); if (idx + 1 < blockStart) atomicAdd(&h_bef[w4.y], 1);
        atomicAdd(&h_all[w4.z], 1); if (idx + 2 < blockStart) atomicAdd(&h_bef[w4.z], 1);
        atomicAdd(&h_all[w4.w], 1); if (idx + 3 < blockStart) atomicAdd(&h_bef[w4.w], 1);
    }
    __syncthreads();

    if (t == 0) {
        int acc = 0;
        for (int l = 1; l <= MAXLEN; ++l) { base[l] = acc; acc += h_all[l]; }
    }
    __syncthreads();

    const int w = blockStart + t;
    if (w < NW) {
        int len  = wl[w];
        int rank = atomicAdd(&h_rank[len], 1);
        int pos  = base[len] + h_bef[len] + rank;
        g_wlen_s[pos] = len;
        g_orig_s[pos] = w;
        unsigned int p[4] = {0u, 0u, 0u, 0u};
        #pragma unroll
        for (int c = 0; c < MAXLEN; ++c) {
            unsigned int ch = (unsigned int)words[w * MAXLEN + c] & 0xFFu;
            p[c >> 2] |= ch << ((c & 3) * 8);
        }
        g_packed[pos] = make_uint4(p[0], p[1], p[2], p[3]);
    }
}

// -------------------------------------------------------------------------
// DP specialized on WLEN (warp-uniform after sort). Straight-line inner loop,
// no branches per cell. smem matrix stores BIASED values:
//   e[r][c] = d[r][c] - r - c + 32     (range [6, 60], fits u8)
// Transposition read:  d[k][l] = e + k + l - 32, so
//   trans = e + (i - k - 1) + 1 + (j - l - 1) + k + l - 32 = e + i + j - 33
// kreg/db kept PRE-SCALED as byte offsets (k*1024, l*64): address = 1 IADD3.
// -------------------------------------------------------------------------
template<int WLEN>
__device__ __noinline__ int dp_run(int swl, const int* s_x, uint4 pw,
                                   unsigned char* bp) {
    int wc[WLEN];
    #pragma unroll
    for (int c = 0; c < WLEN; ++c) {
        unsigned int r = (c < 4) ? pw.x : (c < 8) ? pw.y : (c < 12) ? pw.z : pw.w;
        wc[c] = (int)((r >> ((c & 3) * 8)) & 0xFFu);
    }
    int ks[WLEN];                       // k * 1024 (pre-scaled row offset)
    #pragma unroll
    for (int c = 0; c < WLEN; ++c) ks[c] = 0;

    const int maxd32 = swl + WLEN + 32;
    // Boundary init, biased:
    //  row0: maxd32 - l ; row1: l=0 -> maxd32-1, l>=1 -> 30
    //  col0 (k>=2): maxd32 - k ; col1 (k>=2): 30
    #pragma unroll
    for (int l = 0; l < WLEN; ++l) {
        bp[l * 64]        = (unsigned char)(maxd32 - l);
        bp[1024 + l * 64] = (unsigned char)(l == 0 ? maxd32 - 1 : 30);
    }
    for (int k = 2; k < swl; ++k) {
        bp[(k << 10)]      = (unsigned char)(maxd32 - k);
        bp[(k << 10) + 64] = (unsigned char)30;
    }

    int prev[WLEN + 2];                 // prev[j] = d[i][j] (unbiased)
    #pragma unroll
    for (int j = 1; j <= WLEN + 1; ++j) prev[j] = j - 1;

    int res = WLEN;                     // swl==0: d[1][WLEN+1]
    for (int i = 1; i <= swl; ++i) {
        const int xc    = s_x[i - 1];
        const int i1024 = i << 10;
        const int rowC  = i - 33;       // trans = dtr + rowC + j
        const int rowD  = 30 - i;       // store = m + rowD - j
        int dbs  = 0;                   // l * 64
        int left = i;                   // d[i+1][1]
        unsigned char* rowp = bp + ((i + 1) << 10);
        const bool rkeep = (i <= swl - 2);
        #pragma unroll
        for (int j = 1; j <= WLEN; ++j) {
            const bool p   = (xc == wc[j - 1]);
            const int up   = prev[j + 1];
            const int diag = prev[j];
            const int dtr  = (int)bp[ks[j - 1] + dbs];      // LDS.U8
            const int trans = dtr + rowC + j;
            int m = min(up, left) + 1;
            m = min(m, diag + (p ? 0 : 1));
            m = min(m, trans);
            if (p) { dbs = j * 64; ks[j - 1] = i1024; }
            if (j <= WLEN - 2) {                            // compile-time
                if (rkeep) rowp[(j + 1) * 64] = (unsigned char)(m + rowD - j);
            }
            prev[j] = left;
            left = m;
        }
        prev[WLEN + 1] = left;          // d[i+1][WLEN+1] for next row's 'up'
        res = left;
    }
    return res;
}

// -------------------------------------------------------------------------
__global__ void __launch_bounds__(TPB)
dl_kernel(const int* __restrict__ x, float* __restrict__ out) {
    __shared__ unsigned char d_s[14 * 16 * TPB];   // biased e-matrix, 224 B/thr
    __shared__ int s_x[MAXLEN + 1];

    const int tid  = threadIdx.x;
    const int q    = blockIdx.y;
    const int slot = blockIdx.x * TPB + tid;

    if (tid < MAXLEN + 1) s_x[tid] = x[q * (MAXLEN + 1) + tid];
    __syncthreads();

    // swl = first-argmax (jnp.argmax semantics)
    int swl = 0, best = s_x[0];
    #pragma unroll
    for (int t = 1; t <= MAXLEN; ++t) {
        int v = s_x[t];
        if (v > best) { best = v; swl = t; }
    }

    int wlen = 0, orig = 0;
    uint4 pw = make_uint4(0u, 0u, 0u, 0u);
    if (slot < NW) {
        wlen = g_wlen_s[slot];
        orig = g_orig_s[slot];
        pw   = g_packed[slot];
    }

    unsigned char* bp = d_s + tid;
    int res = 0;
    switch (wlen) {                     // warp-uniform (sorted)
        case  1: res = dp_run< 1>(swl, s_x, pw, bp); break;
        case  2: res = dp_run< 2>(swl, s_x, pw, bp); break;
        case  3: res = dp_run< 3>(swl, s_x, pw, bp); break;
        case  4: res = dp_run< 4>(swl, s_x, pw, bp); break;
        case  5: res = dp_run< 5>(swl, s_x, pw, bp); break;
        case  6: res = dp_run< 6>(swl, s_x, pw, bp); break;
        case  7: res = dp_run< 7>(swl, s_x, pw, bp); break;
        case  8: res = dp_run< 8>(swl, s_x, pw, bp); break;
        case  9: res = dp_run< 9>(swl, s_x, pw, bp); break;
        case 10: res = dp_run<10>(swl, s_x, pw, bp); break;
        case 11: res = dp_run<11>(swl, s_x, pw, bp); break;
        case 12: res = dp_run<12>(swl, s_x, pw, bp); break;
        case 13: res = dp_run<13>(swl, s_x, pw, bp); break;
        case 14: res = dp_run<14>(swl, s_x, pw, bp); break;
        default: break;                 // only slot >= NW
    }

    if (slot < NW) out[q * NW + orig] = (float)res;
}

// -------------------------------------------------------------------------
extern "C" void kernel_launch(void* const* d_in, const int* in_sizes, int n_in,
                              void* d_out, int out_size) {
    const int* x     = (const int*)d_in[0];   // (2,16,15) int32
    const int* words = (const int*)d_in[1];   // (10000,14) int32
    const int* wl    = (const int*)d_in[2];   // (10000,) int32
    float* out = (float*)d_out;               // (2,16,10000) float32

    fused_sort_kernel<<<NSB, SORT_B>>>(words, wl);
    dim3 grid((NW + TPB - 1) / TPB, QCOUNT);
    dl_kernel<<<grid, TPB>>>(x, out);
}

// round 7
// speedup vs baseline: 1.4628x; 1.4628x over previous
#include <cuda_runtime.h>

#define NW      10000
#define MAXLEN  14
#define QCOUNT  32     // BSZ*SEQ
#define TPB     64
#define SORT_B  256
#define NSB     ((NW + SORT_B - 1) / SORT_B)

// Scratch (no allocation allowed)
__device__ int   g_wlen_s[NW];
__device__ int   g_orig_s[NW];
__device__ uint4 g_packed[NW];

// -------------------------------------------------------------------------
// Fused counting-sort: each block rescans wl (L2-hot) for global +
// before-block histograms; no inter-block deps, single launch.
// -------------------------------------------------------------------------
__global__ void __launch_bounds__(SORT_B)
fused_sort_kernel(const int* __restrict__ words, const int* __restrict__ wl) {
    __shared__ int h_all[MAXLEN + 2];
    __shared__ int h_bef[MAXLEN + 2];
    __shared__ int h_rank[MAXLEN + 2];
    __shared__ int base[MAXLEN + 2];

    const int t = threadIdx.x;
    const int blockStart = blockIdx.x * SORT_B;

    if (t <= MAXLEN + 1) { h_all[t] = 0; h_bef[t] = 0; h_rank[t] = 0; }
    __syncthreads();

    const uint4* wl4 = (const uint4*)wl;
    for (int v = t; v < NW / 4; v += SORT_B) {
        uint4 w4 = wl4[v];
        int idx = v * 4;
        atomicAdd(&h_all[w4.x], 1); if (idx + 0 < blockStart) atomicAdd(&h_bef[w4.x], 1);
        atomicAdd(&h_all[w4.y], 1); if (idx + 1 < blockStart) atomicAdd(&h_bef[w4.y], 1);
        atomicAdd(&h_all[w4.z], 1); if (idx + 2 < blockStart) atomicAdd(&h_bef[w4.z], 1);
        atomicAdd(&h_all[w4.w], 1); if (idx + 3 < blockStart) atomicAdd(&h_bef[w4.w], 1);
    }
    __syncthreads();

    if (t == 0) {
        int acc = 0;
        for (int l = 1; l <= MAXLEN; ++l) { base[l] = acc; acc += h_all[l]; }
    }
    __syncthreads();

    const int w = blockStart + t;
    if (w < NW) {
        int len  = wl[w];
        int rank = atomicAdd(&h_rank[len], 1);
        int pos  = base[len] + h_bef[len] + rank;
        g_wlen_s[pos] = len;
        g_orig_s[pos] = w;
        unsigned int p[4] = {0u, 0u, 0u, 0u};
        #pragma unroll
        for (int c = 0; c < MAXLEN; ++c) {
            unsigned int ch = (unsigned int)words[w * MAXLEN + c] & 0xFFu;
            p[c >> 2] |= ch << ((c & 3) * 8);
        }
        g_packed[pos] = make_uint4(p[0], p[1], p[2], p[3]);
    }
}

// -------------------------------------------------------------------------
// Main kernel: R3's proven branchy structure (inline, no templates) with the
// bias transform. smem matrix (16x16 cells x TPB) stores
//   e[r][c] = d[r][c] - r - c + 32                 (range [6,60], fits u8)
// Transposition: d[k][l] = e + k + l - 32
//   trans = d[k][l] + (i-k-1) + 1 + (j-l-1) = e + i + j - 33
// kreg/db kept PRE-SCALED as byte offsets (k*1024, l*64): gather addr = 1 IADD3.
// Stores are UNconditional (16 rows available; garbage cells never gathered:
// reads use k <= swl-1, l <= wlen-1, all genuinely written).
// -------------------------------------------------------------------------
__global__ void __launch_bounds__(TPB)
dl_kernel(const int* __restrict__ x, float* __restrict__ out) {
    __shared__ unsigned char d_s[16 * 16 * TPB];   // biased e-matrix, 256 B/thr
    __shared__ int s_x[MAXLEN + 1];

    const int tid  = threadIdx.x;
    const int q    = blockIdx.y;
    const int slot = blockIdx.x * TPB + tid;

    if (tid < MAXLEN + 1) s_x[tid] = x[q * (MAXLEN + 1) + tid];
    __syncthreads();

    // swl = first-argmax over the 15 chars (jnp.argmax semantics)
    int swl = 0, best = s_x[0];
    #pragma unroll
    for (int t = 1; t <= MAXLEN; ++t) {
        int v = s_x[t];
        if (v > best) { best = v; swl = t; }
    }

    int wlen = 0, orig = 0;
    unsigned int pw0 = 0, pw1 = 0, pw2 = 0, pw3 = 0;
    if (slot < NW) {
        wlen = g_wlen_s[slot];
        orig = g_orig_s[slot];
        uint4 p = g_packed[slot];
        pw0 = p.x; pw1 = p.y; pw2 = p.z; pw3 = p.w;
    }

    int wc[MAXLEN];
    #pragma unroll
    for (int c = 0; c < MAXLEN; ++c) {
        unsigned int r = (c < 4) ? pw0 : (c < 8) ? pw1 : (c < 12) ? pw2 : pw3;
        wc[c] = (int)((r >> ((c & 3) * 8)) & 0xFFu);
    }
    int ks[MAXLEN];                    // k * 1024 (pre-scaled row offset)
    #pragma unroll
    for (int c = 0; c < MAXLEN; ++c) ks[c] = 0;

    const int maxd32 = swl + wlen + 32;
    unsigned char* bp = d_s + tid;

    // Biased boundary init over the gather-reachable region:
    //  row0 (k=0): e = maxd32 - l
    //  row1 (k=1): l=0 -> maxd32-1 ; l>=1 -> (l-1)-1-l+32 = 30
    //  col0 (k>=2): maxd32 - k ; col1 (k>=2): (k-1)-k-1+32 = 30
    for (int l = 0; l < wlen; ++l) {
        bp[l * 64]        = (unsigned char)(maxd32 - l);
        bp[1024 + l * 64] = (unsigned char)(l == 0 ? maxd32 - 1 : 30);
    }
    for (int k = 2; k < swl; ++k) {
        bp[(k << 10)]      = (unsigned char)(maxd32 - k);
        bp[(k << 10) + 64] = (unsigned char)30;
    }

    // prev[j] = d[i][j] (unbiased); row 1: d[1][j] = j-1
    int prev[16];
    #pragma unroll
    for (int j = 1; j <= 15; ++j) prev[j] = j - 1;

    int res = wlen;                    // swl==0: d[1][wlen+1] = wlen
    for (int i = 1; i <= swl; ++i) {   // uniform per block
        const int xc    = s_x[i - 1];
        const int i1024 = i << 10;
        const int rowC  = i - 33;      // trans = dtr + rowC + j
        const int rowD  = 30 - i;      // store = m + rowD - j
        int dbs  = 0;                  // l * 64
        int left = i;                  // d[i+1][1] = i
        unsigned char* rowp = bp + ((i + 1) << 10);
        #pragma unroll
        for (int j = 1; j <= 15; ++j) {
            if (j > wlen || j == 15) { prev[j] = left; break; }   // d[i+1][j]
            const bool p   = (xc == wc[j - 1]);
            const int up   = prev[j + 1];
            const int diag = prev[j];
            const int dtr  = (int)bp[ks[j - 1] + dbs];            // LDS.U8
            const int trans = dtr + rowC + j;
            int m = min(up, left) + 1;
            m = min(m, diag + (p ? 0 : 1));
            m = min(m, trans);
            if (p) { dbs = j * 64; ks[j - 1] = i1024; }
            rowp[(j + 1) * 64] = (unsigned char)(m + rowD - j);   // unconditional
            prev[j] = left;
            left = m;
        }
        res = left;                    // d[i+1][wlen+1]
    }

    if (slot < NW) out[q * NW + orig] = (float)res;
}

// -------------------------------------------------------------------------
extern "C" void kernel_launch(void* const* d_in, const int* in_sizes, int n_in,
                              void* d_out, int out_size) {
    const int* x     = (const int*)d_in[0];   // (2,16,15) int32
    const int* words = (const int*)d_in[1];   // (10000,14) int32
    const int* wl    = (const int*)d_in[2];   // (10000,) int32
    float* out = (float*)d_out;               // (2,16,10000) float32

    fused_sort_kernel<<<NSB, SORT_B>>>(words, wl);
    dim3 grid((NW + TPB - 1) / TPB, QCOUNT);
    dl_kernel<<<grid, TPB>>>(x, out);
}